// round 1
// baseline (speedup 1.0000x reference)
#include <cuda_runtime.h>
#include <cuda_bf16.h>
#include <cstdint>

// Problem constants (fixed by the dataset)
#define HSM_B 4096
#define HSM_N 32768
#define HSM_L 12
#define HSM_K 64

// Scratch for deterministic two-pass reduction (no cudaMalloc allowed).
__device__ float g_partial[HSM_B];

// Kernel 1: one block per batch row b. 12 warps, warp l handles the l-th
// logsumexp over K=64 gathered columns (2 values per lane).
__global__ __launch_bounds__(HSM_L * 32) void hsm_rows_kernel(
    const float* __restrict__ x,
    const int*   __restrict__ brother,
    const int*   __restrict__ p_y)
{
    const int b    = blockIdx.x;
    const int warp = threadIdx.x >> 5;   // l index, 0..11
    const int lane = threadIdx.x & 31;

    const float* __restrict__ row = x + (size_t)b * HSM_N;

    // Gather two of the 64 columns for this l
    const int c0 = brother[warp * HSM_K + lane];
    const int c1 = brother[warp * HSM_K + lane + 32];
    const float v0 = __ldg(row + c0);
    const float v1 = __ldg(row + c1);

    // Warp max
    float m = fmaxf(v0, v1);
    #pragma unroll
    for (int o = 16; o > 0; o >>= 1)
        m = fmaxf(m, __shfl_xor_sync(0xFFFFFFFFu, m, o));

    // Warp sum of exp(v - m)
    float s = __expf(v0 - m) + __expf(v1 - m);
    #pragma unroll
    for (int o = 16; o > 0; o >>= 1)
        s += __shfl_xor_sync(0xFFFFFFFFu, s, o);

    __shared__ float acc[HSM_L];
    if (lane == 0) {
        const float tgt = __ldg(row + p_y[warp]);
        acc[warp] = (m + __logf(s)) - tgt;   // lse_l - x[b, p_y[l]]
    }
    __syncthreads();

    if (threadIdx.x == 0) {
        float t = 0.f;
        #pragma unroll
        for (int i = 0; i < HSM_L; ++i) t += acc[i];
        g_partial[b] = t;
    }
}

// Kernel 2: deterministic fixed-order reduction of the 4096 partials.
__global__ __launch_bounds__(1024) void hsm_reduce_kernel(float* __restrict__ out)
{
    __shared__ float sm[1024];
    float t = 0.f;
    #pragma unroll
    for (int i = threadIdx.x; i < HSM_B; i += 1024)
        t += g_partial[i];
    sm[threadIdx.x] = t;
    __syncthreads();
    #pragma unroll
    for (int s = 512; s > 0; s >>= 1) {
        if (threadIdx.x < s) sm[threadIdx.x] += sm[threadIdx.x + s];
        __syncthreads();
    }
    if (threadIdx.x == 0)
        out[0] = sm[0] * (1.0f / (float)HSM_B);
}

extern "C" void kernel_launch(void* const* d_in, const int* in_sizes, int n_in,
                              void* d_out, int out_size)
{
    const float* x       = (const float*)d_in[0];   // (B, N) f32
    const int*   brother = (const int*)d_in[1];     // (L, K) i32
    const int*   p_y     = (const int*)d_in[2];     // (L,)   i32
    // d_in[3] = y, unused by the reference math
    float* out = (float*)d_out;

    hsm_rows_kernel<<<HSM_B, HSM_L * 32>>>(x, brother, p_y);
    hsm_reduce_kernel<<<1, 1024>>>(out);
}